// round 1
// baseline (speedup 1.0000x reference)
#include <cuda_runtime.h>
#include <math.h>

// Problem constants
#define BQ 16
#define TT 2048
#define ED 1024
#define AD 512
#define DD 1024
#define CD 64
#define KSY 2
#define CK 15
#define KW 31          // 2*CK+1
#define MM (BQ*TT)     // 32768 rows

// GEMM tiling
#define BM 128
#define BN 128
#define BK 16

// Scratch (static __device__ — no allocations allowed)
__device__ float g_convT[MM * CD];      // conv features, row-major [m, c]  (8 MB)
__device__ float g_decproj[BQ * AD];    // dec projection + b_enc
__device__ float g_score[MM];           // pre-softmax scores

// ---------------------------------------------------------------------------
// Conv1d over time: attn_state [B, 2, T] -> convT [b*T+t, 64]
// ---------------------------------------------------------------------------
__global__ void conv_kernel(const float* __restrict__ state,
                            const float* __restrict__ Wc) {
    __shared__ float sW[CD * KSY * KW];   // 3968 floats
    int tid = threadIdx.x;
    for (int i = tid; i < CD * KSY * KW; i += 256) sW[i] = Wc[i];
    __syncthreads();

    int b = blockIdx.y;
    int c = tid & 63;
    int t = blockIdx.x * 4 + (tid >> 6);

    const float* s0 = state + (b * KSY + 0) * TT;
    const float* s1 = state + (b * KSY + 1) * TT;
    const float* w0 = &sW[(c * KSY + 0) * KW];
    const float* w1 = &sW[(c * KSY + 1) * KW];

    float acc = 0.f;
#pragma unroll
    for (int h = 0; h < KW; ++h) {
        int tt = t + h - CK;
        bool ok = (tt >= 0) && (tt < TT);
        float v0 = ok ? s0[tt] : 0.f;
        float v1 = ok ? s1[tt] : 0.f;
        acc = fmaf(v0, w0[h], acc);
        acc = fmaf(v1, w1[h], acc);
    }
    g_convT[(b * TT + t) * CD + c] = acc;
}

// ---------------------------------------------------------------------------
// dec projection: decproj[b,a] = decoder_h[b,:] . W_dec[a,:] + b_enc[a]
// ---------------------------------------------------------------------------
__global__ void dec_kernel(const float* __restrict__ h,
                           const float* __restrict__ Wd,
                           const float* __restrict__ be) {
    int idx = blockIdx.x * 256 + threadIdx.x;   // b*AD + a
    int b = idx >> 9;
    int a = idx & (AD - 1);
    const float4* hv = (const float4*)(h + b * DD);
    const float4* wv = (const float4*)(Wd + (size_t)a * DD);
    float acc = 0.f;
#pragma unroll 8
    for (int k = 0; k < DD / 4; ++k) {
        float4 x = hv[k], w = wv[k];
        acc = fmaf(x.x, w.x, acc);
        acc = fmaf(x.y, w.y, acc);
        acc = fmaf(x.z, w.z, acc);
        acc = fmaf(x.w, w.w, acc);
    }
    g_decproj[idx] = acc + be[a];
}

// ---------------------------------------------------------------------------
// score init (b_out) + zero context region of d_out
// ---------------------------------------------------------------------------
__global__ void init_kernel(const float* __restrict__ b_out, float* __restrict__ cctx) {
    int i = blockIdx.x * 256 + threadIdx.x;
    if (i < MM) g_score[i] = b_out[0];
    if (i < BQ * ED) cctx[i] = 0.f;
}

// ---------------------------------------------------------------------------
// Fused GEMM: z[m,a] = enc[m,:1024].W_enc[a,:] + conv[m,:64].W_attn[a,:]
//             + decproj[b,a]; score[m] += sum_a tanh(z)*W_out[a]
// ---------------------------------------------------------------------------
__global__ __launch_bounds__(256, 2)
void fused_gemm(const float* __restrict__ A1,    // encoder_out [MM,1024]
                const float* __restrict__ W1,    // W_enc [512,1024]
                const float* __restrict__ W2,    // W_attn [512,64]
                const float* __restrict__ Wout)  // W_out [512]
{
    __shared__ float As[BK][BM];
    __shared__ float Bs[BK][BN];

    int tid = threadIdx.x;
    int tx = tid & 15, ty = tid >> 4;
    int rowBase = blockIdx.y * BM;
    int colBase = blockIdx.x * BN;

    float acc[8][8];
#pragma unroll
    for (int i = 0; i < 8; ++i)
#pragma unroll
        for (int j = 0; j < 8; ++j) acc[i][j] = 0.f;

    // ---- segment 1: K = 1024 over encoder / W_enc ----
    {
        const float* Ap = A1 + (size_t)rowBase * ED;
        const float* Bp = W1 + (size_t)colBase * ED;
        for (int k0 = 0; k0 < ED; k0 += BK) {
            __syncthreads();
#pragma unroll
            for (int i = 0; i < 2; ++i) {
                int s = i * 256 + tid;
                int r = s & 127, kq = s >> 7;
                float4 v = *(const float4*)(Ap + (size_t)r * ED + k0 + kq * 4);
                As[kq * 4 + 0][r] = v.x; As[kq * 4 + 1][r] = v.y;
                As[kq * 4 + 2][r] = v.z; As[kq * 4 + 3][r] = v.w;
                float4 w = *(const float4*)(Bp + (size_t)r * ED + k0 + kq * 4);
                Bs[kq * 4 + 0][r] = w.x; Bs[kq * 4 + 1][r] = w.y;
                Bs[kq * 4 + 2][r] = w.z; Bs[kq * 4 + 3][r] = w.w;
            }
            __syncthreads();
#pragma unroll
            for (int k = 0; k < BK; ++k) {
                float ra[8], rb[8];
                *(float4*)&ra[0] = *(const float4*)&As[k][ty * 8];
                *(float4*)&ra[4] = *(const float4*)&As[k][ty * 8 + 4];
                *(float4*)&rb[0] = *(const float4*)&Bs[k][tx * 8];
                *(float4*)&rb[4] = *(const float4*)&Bs[k][tx * 8 + 4];
#pragma unroll
                for (int i = 0; i < 8; ++i)
#pragma unroll
                    for (int j = 0; j < 8; ++j)
                        acc[i][j] = fmaf(ra[i], rb[j], acc[i][j]);
            }
        }
    }

    // ---- segment 2: K = 64 over convT / W_attn ----
    {
        const float* Ap = g_convT + (size_t)rowBase * CD;
        const float* Bp = W2 + (size_t)colBase * CD;
        for (int k0 = 0; k0 < CD; k0 += BK) {
            __syncthreads();
#pragma unroll
            for (int i = 0; i < 2; ++i) {
                int s = i * 256 + tid;
                int r = s & 127, kq = s >> 7;
                float4 v = *(const float4*)(Ap + (size_t)r * CD + k0 + kq * 4);
                As[kq * 4 + 0][r] = v.x; As[kq * 4 + 1][r] = v.y;
                As[kq * 4 + 2][r] = v.z; As[kq * 4 + 3][r] = v.w;
                float4 w = *(const float4*)(Bp + (size_t)r * CD + k0 + kq * 4);
                Bs[kq * 4 + 0][r] = w.x; Bs[kq * 4 + 1][r] = w.y;
                Bs[kq * 4 + 2][r] = w.z; Bs[kq * 4 + 3][r] = w.w;
            }
            __syncthreads();
#pragma unroll
            for (int k = 0; k < BK; ++k) {
                float ra[8], rb[8];
                *(float4*)&ra[0] = *(const float4*)&As[k][ty * 8];
                *(float4*)&ra[4] = *(const float4*)&As[k][ty * 8 + 4];
                *(float4*)&rb[0] = *(const float4*)&Bs[k][tx * 8];
                *(float4*)&rb[4] = *(const float4*)&Bs[k][tx * 8 + 4];
#pragma unroll
                for (int i = 0; i < 8; ++i)
#pragma unroll
                    for (int j = 0; j < 8; ++j)
                        acc[i][j] = fmaf(ra[i], rb[j], acc[i][j]);
            }
        }
    }

    // ---- epilogue: +decproj, tanh, dot W_out, reduce over a ----
    float wo[8];
#pragma unroll
    for (int j = 0; j < 8; ++j) wo[j] = Wout[colBase + tx * 8 + j];

    int b = rowBase >> 11;   // T = 2048, BM = 128 => whole tile in one batch
    const float* dp = g_decproj + b * AD + colBase + tx * 8;

#pragma unroll
    for (int i = 0; i < 8; ++i) {
        int row = rowBase + ty * 8 + i;
        float partial = 0.f;
#pragma unroll
        for (int j = 0; j < 8; ++j) {
            float z = acc[i][j] + dp[j];
            partial = fmaf(tanhf(z), wo[j], partial);
        }
        // reduce across tx (lanes 0..15 / 16..31 hold same rows)
        partial += __shfl_xor_sync(0xffffffffu, partial, 1);
        partial += __shfl_xor_sync(0xffffffffu, partial, 2);
        partial += __shfl_xor_sync(0xffffffffu, partial, 4);
        partial += __shfl_xor_sync(0xffffffffu, partial, 8);
        if (tx == 0) atomicAdd(&g_score[row], partial);
    }
}

// ---------------------------------------------------------------------------
// softmax over T per batch: w[b,t] = softmax(2*score[b,:])
// ---------------------------------------------------------------------------
__global__ void softmax_kernel(const unsigned char* __restrict__ mask,
                               float* __restrict__ wout) {
    __shared__ float red[256];
    int b = blockIdx.x;
    int tid = threadIdx.x;

    float local[8];
    float mx = -INFINITY;
#pragma unroll
    for (int i = 0; i < 8; ++i) {
        int t = i * 256 + tid;
        float v = g_score[b * TT + t];
        if (mask[b * TT + t]) v = -INFINITY;
        local[i] = v;
        mx = fmaxf(mx, v);
    }
    red[tid] = mx; __syncthreads();
    for (int s = 128; s > 0; s >>= 1) {
        if (tid < s) red[tid] = fmaxf(red[tid], red[tid + s]);
        __syncthreads();
    }
    mx = red[0]; __syncthreads();

    float sum = 0.f;
#pragma unroll
    for (int i = 0; i < 8; ++i) {
        local[i] = expf(2.f * (local[i] - mx));
        sum += local[i];
    }
    red[tid] = sum; __syncthreads();
    for (int s = 128; s > 0; s >>= 1) {
        if (tid < s) red[tid] += red[tid + s];
        __syncthreads();
    }
    float inv = 1.f / red[0];
#pragma unroll
    for (int i = 0; i < 8; ++i)
        wout[b * TT + i * 256 + tid] = local[i] * inv;
}

// ---------------------------------------------------------------------------
// context: c[b,e] = sum_t enc[b,t,e] * w[b,t]   (t-chunked, atomic accumulate)
// ---------------------------------------------------------------------------
__global__ void context_kernel(const float* __restrict__ enc,
                               const float* __restrict__ w,
                               float* __restrict__ c) {
    __shared__ float sw[256];
    int b = blockIdx.z;
    int e = blockIdx.x * 256 + threadIdx.x;
    int t0 = blockIdx.y * 256;
    sw[threadIdx.x] = w[b * TT + t0 + threadIdx.x];
    __syncthreads();

    const float* ep = enc + ((size_t)(b * TT + t0)) * ED + e;
    float acc = 0.f;
#pragma unroll 4
    for (int t = 0; t < 256; ++t)
        acc = fmaf(ep[(size_t)t * ED], sw[t], acc);
    atomicAdd(&c[b * ED + e], acc);
}

// ---------------------------------------------------------------------------
// launch
// ---------------------------------------------------------------------------
extern "C" void kernel_launch(void* const* d_in, const int* in_sizes, int n_in,
                              void* d_out, int out_size) {
    const float*         encoder_out = (const float*)d_in[0];
    const unsigned char* mask        = (const unsigned char*)d_in[1];
    const float*         decoder_h   = (const float*)d_in[2];
    const float*         attn_state  = (const float*)d_in[3];
    const float*         W_enc       = (const float*)d_in[4];
    const float*         b_enc       = (const float*)d_in[5];
    const float*         W_dec       = (const float*)d_in[6];
    const float*         W_attn      = (const float*)d_in[7];
    const float*         W_conv      = (const float*)d_in[8];
    const float*         W_out       = (const float*)d_in[9];
    const float*         b_out       = (const float*)d_in[10];

    float* out_c = (float*)d_out;               // [B, ED]
    float* out_w = (float*)d_out + BQ * ED;     // [B, T]

    conv_kernel<<<dim3(TT / 4, BQ), 256>>>(attn_state, W_conv);
    dec_kernel<<<(BQ * AD) / 256, 256>>>(decoder_h, W_dec, b_enc);
    init_kernel<<<MM / 256, 256>>>(b_out, out_c);
    fused_gemm<<<dim3(AD / BN, MM / BM), 256>>>(encoder_out, W_enc, W_attn, W_out);
    softmax_kernel<<<BQ, 256>>>(mask, out_w);
    context_kernel<<<dim3(ED / 256, TT / 256, BQ), 256>>>(encoder_out, out_w, out_c);
}

// round 4
// speedup vs baseline: 2.5700x; 2.5700x over previous
#include <cuda_runtime.h>
#include <cuda_fp16.h>
#include <math.h>
#include <stdint.h>

// ---------------- problem constants ----------------
#define BQ 16
#define TT 2048
#define ED 1024
#define AD 512
#define DD 1024
#define CD 64
#define KSY 2
#define CK 15
#define KW 31
#define MM (BQ*TT)
#define KK 1088            // ED + CD concatenated K

// ---------------- GEMM tiling ----------------
#define BM 128
#define BN 256
#define BK 32
#define NKIT (KK/BK)       // 34
#define NSTAGE 3
#define STAGE_BYTES 32768  // Ah 8K + Al 8K + B 16K
#define SMEM_REQ (NSTAGE*STAGE_BYTES)
#define NTHREADS 512       // 16 warps: 2 (m) x 8 (n), warp tile 64x32

// ---------------- scratch ----------------
__device__ __half g_Ah[(size_t)MM*KK];
__device__ __half g_Al[(size_t)MM*KK];
__device__ __half g_Bh[(size_t)AD*KK];
__device__ float  g_decproj[BQ*AD];
__device__ float  g_score[MM];

// ---------------- helpers ----------------
__device__ __forceinline__ uint32_t smem_u32(const void* p){
    uint32_t a;
    asm("{ .reg .u64 t; cvta.to.shared.u64 t, %1; cvt.u32.u64 %0, t; }" : "=r"(a) : "l"(p));
    return a;
}
__device__ __forceinline__ void cp16(uint32_t dst, const void* src){
    asm volatile("cp.async.cg.shared.global [%0], [%1], 16;" :: "r"(dst), "l"(src) : "memory");
}
// 64B rows, 16B granules, XOR swizzle for conflict-free ldmatrix
__device__ __forceinline__ uint32_t swz(uint32_t r, uint32_t g){
    return r * 64u + ((g ^ ((r >> 1) & 3u)) << 4);
}
#define MMA16816(d, a, b) \
    asm volatile("mma.sync.aligned.m16n8k16.row.col.f32.f16.f16.f32 " \
        "{%0,%1,%2,%3}, {%4,%5,%6,%7}, {%8,%9}, {%0,%1,%2,%3};" \
        : "+f"((d)[0]), "+f"((d)[1]), "+f"((d)[2]), "+f"((d)[3]) \
        : "r"((a)[0]), "r"((a)[1]), "r"((a)[2]), "r"((a)[3]), \
          "r"((b)[0]), "r"((b)[1]))

// ---------------- prep: split encoder into fp16 hi/lo ----------------
__global__ void enc_split(const float* __restrict__ enc){
    size_t i = (size_t)blockIdx.x * 256 + threadIdx.x;   // float4 index
    size_t e = i * 4;
    size_t m = e >> 10;
    int k = (int)(e & 1023);
    float4 v = *(const float4*)(enc + e);
    float xs[4] = {v.x, v.y, v.z, v.w};
    union { __half h[4]; uint2 u; } H, L;
#pragma unroll
    for (int j = 0; j < 4; ++j){
        __half hi = __float2half_rn(xs[j]);
        H.h[j] = hi;
        L.h[j] = __float2half_rn(xs[j] - __half2float(hi));
    }
    size_t d = m * KK + k;
    *(uint2*)(g_Ah + d) = H.u;
    *(uint2*)(g_Al + d) = L.u;
}

// ---------------- prep: conv over time -> A cols [1024,1088) ----------------
__global__ void conv_split(const float* __restrict__ state,
                           const float* __restrict__ Wc){
    __shared__ float sW[CD * KSY * KW];
    int tid = threadIdx.x;
    for (int i = tid; i < CD * KSY * KW; i += 256) sW[i] = Wc[i];
    __syncthreads();

    int b = blockIdx.y;
    int c = tid & 63;
    int t = blockIdx.x * 4 + (tid >> 6);

    const float* s0 = state + (b * KSY + 0) * TT;
    const float* s1 = state + (b * KSY + 1) * TT;
    const float* w0 = &sW[(c * KSY + 0) * KW];
    const float* w1 = &sW[(c * KSY + 1) * KW];

    float acc = 0.f;
#pragma unroll
    for (int h = 0; h < KW; ++h){
        int tt = t + h - CK;
        bool ok = (tt >= 0) && (tt < TT);
        float v0 = ok ? s0[tt] : 0.f;
        float v1 = ok ? s1[tt] : 0.f;
        acc = fmaf(v0, w0[h], acc);
        acc = fmaf(v1, w1[h], acc);
    }
    __half hi = __float2half_rn(acc);
    size_t d = (size_t)(b * TT + t) * KK + ED + c;
    g_Ah[d] = hi;
    g_Al[d] = __float2half_rn(acc - __half2float(hi));
}

// ---------------- prep: weights fp16, concatenated K ----------------
__global__ void w_split(const float* __restrict__ We, const float* __restrict__ Wa){
    int n = blockIdx.x;
    for (int k = threadIdx.x; k < KK; k += 256){
        float x = (k < ED) ? We[(size_t)n * ED + k] : Wa[n * CD + (k - ED)];
        g_Bh[(size_t)n * KK + k] = __float2half_rn(x);
    }
}

// ---------------- prep: decoder projection + b_enc ----------------
__global__ void dec_kernel(const float* __restrict__ h,
                           const float* __restrict__ Wd,
                           const float* __restrict__ be){
    int idx = blockIdx.x * 256 + threadIdx.x;
    int b = idx >> 9;
    int a = idx & (AD - 1);
    const float4* hv = (const float4*)(h + b * DD);
    const float4* wv = (const float4*)(Wd + (size_t)a * DD);
    float acc = 0.f;
#pragma unroll 8
    for (int k = 0; k < DD / 4; ++k){
        float4 x = hv[k], w = wv[k];
        acc = fmaf(x.x, w.x, acc); acc = fmaf(x.y, w.y, acc);
        acc = fmaf(x.z, w.z, acc); acc = fmaf(x.w, w.w, acc);
    }
    g_decproj[idx] = acc + be[a];
}

__global__ void init_kernel(const float* __restrict__ b_out, float* __restrict__ cctx){
    int i = blockIdx.x * 256 + threadIdx.x;
    if (i < MM) g_score[i] = b_out[0];
    if (i < BQ * ED) cctx[i] = 0.f;
}

// ---------------- stage loader: 2048 x 16B cp.async per stage ----------------
__device__ __forceinline__ void load_stage(uint32_t st, int rowBase, int colBase,
                                           int k0, int tid){
#pragma unroll
    for (int j = 0; j < 4; ++j){
        int i = tid + j * 512;
        const __half* gp;
        uint32_t dst;
        if (i < 1024){
            int r = (i & 511) >> 2, g = i & 3;
            const __half* base = (i < 512) ? g_Ah : g_Al;
            gp = base + (size_t)(rowBase + r) * KK + k0 + g * 8;
            dst = st + (i < 512 ? 0u : 8192u) + swz(r, g);
        } else {
            int idx = i - 1024;
            int r = idx >> 2, g = idx & 3;
            gp = g_Bh + (size_t)(colBase + r) * KK + k0 + g * 8;
            dst = st + 16384u + swz(r, g);
        }
        cp16(dst, gp);
    }
    asm volatile("cp.async.commit_group;" ::: "memory");
}

// ---------------- fp16 split-K GEMM + fused epilogue ----------------
__global__ void __launch_bounds__(NTHREADS, 1)
mma_kernel(const float* __restrict__ Wout){
    extern __shared__ char smraw[];
    uint32_t sbase = smem_u32(smraw);
    int tid = threadIdx.x;
    int lane = tid & 31;
    int wid = tid >> 5;
    int warp_m = wid & 1;       // 0..1  -> 64 rows each
    int warp_n = wid >> 1;      // 0..7  -> 32 cols each
    int rowBase = blockIdx.y * BM;
    int colBase = blockIdx.x * BN;

    // ldmatrix within-tile offsets
    uint32_t offA[4][2], offB[4][2];
#pragma unroll
    for (int fm = 0; fm < 4; ++fm)
#pragma unroll
        for (int k16 = 0; k16 < 2; ++k16){
            uint32_t r = warp_m * 64 + fm * 16 + (lane & 15);
            uint32_t g = k16 * 2 + (lane >> 4);
            offA[fm][k16] = swz(r, g);
        }
#pragma unroll
    for (int fn = 0; fn < 4; ++fn)
#pragma unroll
        for (int k16 = 0; k16 < 2; ++k16){
            uint32_t r = warp_n * 32 + fn * 8 + (lane & 7);
            uint32_t g = k16 * 2 + ((lane >> 3) & 1);
            offB[fn][k16] = swz(r, g);
        }

    float acc[4][4][4];
#pragma unroll
    for (int fm = 0; fm < 4; ++fm)
#pragma unroll
        for (int fn = 0; fn < 4; ++fn)
#pragma unroll
            for (int q = 0; q < 4; ++q) acc[fm][fn][q] = 0.f;

    load_stage(sbase + 0 * STAGE_BYTES, rowBase, colBase, 0, tid);
    load_stage(sbase + 1 * STAGE_BYTES, rowBase, colBase, BK, tid);

    for (int it = 0; it < NKIT; ++it){
        if (it + 2 < NKIT)
            load_stage(sbase + ((it + 2) % NSTAGE) * STAGE_BYTES,
                       rowBase, colBase, (it + 2) * BK, tid);
        else
            asm volatile("cp.async.commit_group;" ::: "memory");
        asm volatile("cp.async.wait_group 2;" ::: "memory");
        __syncthreads();

        uint32_t st = sbase + (it % NSTAGE) * STAGE_BYTES;
        uint32_t sAh = st, sAl = st + 8192u, sB = st + 16384u;

#pragma unroll
        for (int k16 = 0; k16 < 2; ++k16){
            uint32_t b[4][2];
#pragma unroll
            for (int fn = 0; fn < 4; ++fn)
                asm volatile("ldmatrix.sync.aligned.m8n8.x2.shared.b16 {%0,%1}, [%2];"
                    : "=r"(b[fn][0]), "=r"(b[fn][1]) : "r"(sB + offB[fn][k16]));
            uint32_t a[4][4];
#pragma unroll
            for (int fm = 0; fm < 4; ++fm)
                asm volatile("ldmatrix.sync.aligned.m8n8.x4.shared.b16 {%0,%1,%2,%3}, [%4];"
                    : "=r"(a[fm][0]), "=r"(a[fm][1]), "=r"(a[fm][2]), "=r"(a[fm][3])
                    : "r"(sAh + offA[fm][k16]));
#pragma unroll
            for (int fm = 0; fm < 4; ++fm)
#pragma unroll
                for (int fn = 0; fn < 4; ++fn)
                    MMA16816(acc[fm][fn], a[fm], b[fn]);
            // low-A correction pass (reuse a regs)
#pragma unroll
            for (int fm = 0; fm < 4; ++fm)
                asm volatile("ldmatrix.sync.aligned.m8n8.x4.shared.b16 {%0,%1,%2,%3}, [%4];"
                    : "=r"(a[fm][0]), "=r"(a[fm][1]), "=r"(a[fm][2]), "=r"(a[fm][3])
                    : "r"(sAl + offA[fm][k16]));
#pragma unroll
            for (int fm = 0; fm < 4; ++fm)
#pragma unroll
                for (int fn = 0; fn < 4; ++fn)
                    MMA16816(acc[fm][fn], a[fm], b[fn]);
        }
        __syncthreads();
    }

    // ---- epilogue: +decproj, tanh, dot W_out, reduce + atomic ----
    int b = rowBase >> 11;
    float wo[4][2], dp[4][2];
#pragma unroll
    for (int fn = 0; fn < 4; ++fn){
        int c0 = colBase + warp_n * 32 + fn * 8 + 2 * (lane & 3);
        wo[fn][0] = Wout[c0];               wo[fn][1] = Wout[c0 + 1];
        dp[fn][0] = g_decproj[b * AD + c0]; dp[fn][1] = g_decproj[b * AD + c0 + 1];
    }
    int g = lane >> 2;
#pragma unroll
    for (int fm = 0; fm < 4; ++fm){
        float s0 = 0.f, s1 = 0.f;
#pragma unroll
        for (int fn = 0; fn < 4; ++fn){
            s0 += tanhf(acc[fm][fn][0] + dp[fn][0]) * wo[fn][0];
            s0 += tanhf(acc[fm][fn][1] + dp[fn][1]) * wo[fn][1];
            s1 += tanhf(acc[fm][fn][2] + dp[fn][0]) * wo[fn][0];
            s1 += tanhf(acc[fm][fn][3] + dp[fn][1]) * wo[fn][1];
        }
        s0 += __shfl_xor_sync(~0u, s0, 1); s0 += __shfl_xor_sync(~0u, s0, 2);
        s1 += __shfl_xor_sync(~0u, s1, 1); s1 += __shfl_xor_sync(~0u, s1, 2);
        if ((lane & 3) == 0){
            int row = rowBase + warp_m * 64 + fm * 16 + g;
            atomicAdd(&g_score[row], s0);
            atomicAdd(&g_score[row + 8], s1);
        }
    }
}

// ---------------- softmax over T per batch ----------------
__global__ void softmax_kernel(const unsigned char* __restrict__ mask,
                               float* __restrict__ wout){
    __shared__ float red[256];
    int b = blockIdx.x;
    int tid = threadIdx.x;

    float local[8];
    float mx = -INFINITY;
#pragma unroll
    for (int i = 0; i < 8; ++i){
        int t = i * 256 + tid;
        float v = g_score[b * TT + t];
        if (mask[b * TT + t]) v = -INFINITY;
        local[i] = v;
        mx = fmaxf(mx, v);
    }
    red[tid] = mx; __syncthreads();
    for (int s = 128; s > 0; s >>= 1){
        if (tid < s) red[tid] = fmaxf(red[tid], red[tid + s]);
        __syncthreads();
    }
    mx = red[0]; __syncthreads();

    float sum = 0.f;
#pragma unroll
    for (int i = 0; i < 8; ++i){
        local[i] = expf(2.f * (local[i] - mx));
        sum += local[i];
    }
    red[tid] = sum; __syncthreads();
    for (int s = 128; s > 0; s >>= 1){
        if (tid < s) red[tid] += red[tid + s];
        __syncthreads();
    }
    float inv = 1.f / red[0];
#pragma unroll
    for (int i = 0; i < 8; ++i)
        wout[b * TT + i * 256 + tid] = local[i] * inv;
}

// ---------------- context ----------------
__global__ void context_kernel(const float* __restrict__ enc,
                               const float* __restrict__ w,
                               float* __restrict__ c){
    __shared__ float sw[256];
    int b = blockIdx.z;
    int e = blockIdx.x * 256 + threadIdx.x;
    int t0 = blockIdx.y * 256;
    sw[threadIdx.x] = w[b * TT + t0 + threadIdx.x];
    __syncthreads();

    const float* ep = enc + ((size_t)(b * TT + t0)) * ED + e;
    float acc = 0.f;
#pragma unroll 4
    for (int t = 0; t < 256; ++t)
        acc = fmaf(ep[(size_t)t * ED], sw[t], acc);
    atomicAdd(&c[b * ED + e], acc);
}

// ---------------- launch ----------------
extern "C" void kernel_launch(void* const* d_in, const int* in_sizes, int n_in,
                              void* d_out, int out_size){
    const float*         encoder_out = (const float*)d_in[0];
    const unsigned char* mask        = (const unsigned char*)d_in[1];
    const float*         decoder_h   = (const float*)d_in[2];
    const float*         attn_state  = (const float*)d_in[3];
    const float*         W_enc       = (const float*)d_in[4];
    const float*         b_enc       = (const float*)d_in[5];
    const float*         W_dec       = (const float*)d_in[6];
    const float*         W_attn      = (const float*)d_in[7];
    const float*         W_conv      = (const float*)d_in[8];
    const float*         W_out       = (const float*)d_in[9];
    const float*         b_out       = (const float*)d_in[10];

    float* out_c = (float*)d_out;               // [B, ED]
    float* out_w = (float*)d_out + BQ * ED;     // [B, T]

    cudaFuncSetAttribute(mma_kernel, cudaFuncAttributeMaxDynamicSharedMemorySize, SMEM_REQ);

    enc_split<<<(MM * ED / 4) / 256, 256>>>(encoder_out);
    conv_split<<<dim3(TT / 4, BQ), 256>>>(attn_state, W_conv);
    w_split<<<AD, 256>>>(W_enc, W_attn);
    dec_kernel<<<(BQ * AD) / 256, 256>>>(decoder_h, W_dec, b_enc);
    init_kernel<<<MM / 256, 256>>>(b_out, out_c);
    mma_kernel<<<dim3(AD / BN, MM / BM), NTHREADS, SMEM_REQ>>>(W_out);
    softmax_kernel<<<BQ, 256>>>(mask, out_w);
    context_kernel<<<dim3(ED / 256, TT / 256, BQ), 256>>>(encoder_out, out_w, out_c);
}

// round 7
// speedup vs baseline: 2.9671x; 1.1545x over previous
#include <cuda_runtime.h>
#include <cuda_fp16.h>
#include <math.h>
#include <stdint.h>

// ---------------- problem constants ----------------
#define BQ 16
#define TT 2048
#define ED 1024
#define AD 512
#define DD 1024
#define CD 64
#define KSY 2
#define CK 15
#define KW 31
#define MM (BQ*TT)
#define KK 1088            // ED + CD concatenated K

// ---------------- GEMM tiling ----------------
#define BM 128
#define BN 256
#define BK 32
#define NKIT (KK/BK)       // 34
#define NSTAGE 3
#define STAGE_BYTES 32768  // Ah 8K + Al 8K + B 16K
#define SMEM_REQ (NSTAGE*STAGE_BYTES)
#define NTHREADS 512       // 16 warps: 2 (m) x 8 (n), warp tile 64x32

// ---------------- scratch ----------------
__device__ __half g_Ah[(size_t)MM*KK];
__device__ __half g_Al[(size_t)MM*KK];
__device__ __half g_Bh[(size_t)AD*KK];
__device__ float  g_decproj[BQ*AD];
__device__ float  g_score[MM];

// ---------------- helpers ----------------
__device__ __forceinline__ uint32_t smem_u32(const void* p){
    uint32_t a;
    asm("{ .reg .u64 t; cvta.to.shared.u64 t, %1; cvt.u32.u64 %0, t; }" : "=r"(a) : "l"(p));
    return a;
}
__device__ __forceinline__ void cp16(uint32_t dst, const void* src){
    asm volatile("cp.async.cg.shared.global [%0], [%1], 16;" :: "r"(dst), "l"(src) : "memory");
}
// 64B rows, 16B granules, XOR swizzle for conflict-free ldmatrix
__device__ __forceinline__ uint32_t swz(uint32_t r, uint32_t g){
    return r * 64u + ((g ^ ((r >> 1) & 3u)) << 4);
}
#define MMA16816(d, a, b) \
    asm volatile("mma.sync.aligned.m16n8k16.row.col.f32.f16.f16.f32 " \
        "{%0,%1,%2,%3}, {%4,%5,%6,%7}, {%8,%9}, {%0,%1,%2,%3};" \
        : "+f"((d)[0]), "+f"((d)[1]), "+f"((d)[2]), "+f"((d)[3]) \
        : "r"((a)[0]), "r"((a)[1]), "r"((a)[2]), "r"((a)[3]), \
          "r"((b)[0]), "r"((b)[1]))

// ---------------- prep: split encoder into fp16 hi/lo ----------------
__global__ void enc_split(const float* __restrict__ enc){
    size_t i = (size_t)blockIdx.x * 256 + threadIdx.x;   // float4 index
    size_t e = i * 4;
    size_t m = e >> 10;
    int k = (int)(e & 1023);
    float4 v = *(const float4*)(enc + e);
    float xs[4] = {v.x, v.y, v.z, v.w};
    union { __half h[4]; uint2 u; } H, L;
#pragma unroll
    for (int j = 0; j < 4; ++j){
        __half hi = __float2half_rn(xs[j]);
        H.h[j] = hi;
        L.h[j] = __float2half_rn(xs[j] - __half2float(hi));
    }
    size_t d = m * KK + k;
    *(uint2*)(g_Ah + d) = H.u;
    *(uint2*)(g_Al + d) = L.u;
}

// ---------------- prep: conv over time -> A cols [1024,1088) ----------------
__global__ void conv_split(const float* __restrict__ state,
                           const float* __restrict__ Wc){
    __shared__ float sW[CD * KSY * KW];
    int tid = threadIdx.x;
    for (int i = tid; i < CD * KSY * KW; i += 256) sW[i] = Wc[i];
    __syncthreads();

    int b = blockIdx.y;
    int c = tid & 63;
    int t = blockIdx.x * 4 + (tid >> 6);

    const float* s0 = state + (b * KSY + 0) * TT;
    const float* s1 = state + (b * KSY + 1) * TT;
    const float* w0 = &sW[(c * KSY + 0) * KW];
    const float* w1 = &sW[(c * KSY + 1) * KW];

    float acc = 0.f;
#pragma unroll
    for (int h = 0; h < KW; ++h){
        int tt = t + h - CK;
        bool ok = (tt >= 0) && (tt < TT);
        float v0 = ok ? s0[tt] : 0.f;
        float v1 = ok ? s1[tt] : 0.f;
        acc = fmaf(v0, w0[h], acc);
        acc = fmaf(v1, w1[h], acc);
    }
    __half hi = __float2half_rn(acc);
    size_t d = (size_t)(b * TT + t) * KK + ED + c;
    g_Ah[d] = hi;
    g_Al[d] = __float2half_rn(acc - __half2float(hi));
}

// ---------------- prep: weights fp16, concatenated K ----------------
__global__ void w_split(const float* __restrict__ We, const float* __restrict__ Wa){
    int n = blockIdx.x;
    for (int k = threadIdx.x; k < KK; k += 256){
        float x = (k < ED) ? We[(size_t)n * ED + k] : Wa[n * CD + (k - ED)];
        g_Bh[(size_t)n * KK + k] = __float2half_rn(x);
    }
}

// ---------------- prep: decoder projection, warp-per-output ----------------
__global__ void dec_kernel(const float* __restrict__ h,
                           const float* __restrict__ Wd,
                           const float* __restrict__ be){
    int wgid = (blockIdx.x * 256 + threadIdx.x) >> 5;   // 0..8191
    int lane = threadIdx.x & 31;
    int b = wgid >> 9;
    int a = wgid & (AD - 1);
    const float4* hv = (const float4*)(h + b * DD) + lane;
    const float4* wv = (const float4*)(Wd + (size_t)a * DD) + lane;
    float acc = 0.f;
#pragma unroll
    for (int k = 0; k < 8; ++k){
        float4 x = hv[k * 32], w = wv[k * 32];
        acc = fmaf(x.x, w.x, acc); acc = fmaf(x.y, w.y, acc);
        acc = fmaf(x.z, w.z, acc); acc = fmaf(x.w, w.w, acc);
    }
#pragma unroll
    for (int s = 16; s > 0; s >>= 1) acc += __shfl_xor_sync(~0u, acc, s);
    if (lane == 0) g_decproj[wgid] = acc + be[a];
}

__global__ void init_kernel(const float* __restrict__ b_out, float* __restrict__ cctx){
    int i = blockIdx.x * 256 + threadIdx.x;
    if (i < MM) g_score[i] = b_out[0];
    if (i < BQ * ED) cctx[i] = 0.f;
}

// ---------------- stage loader: 2048 x 16B cp.async per stage ----------------
__device__ __forceinline__ void load_stage(uint32_t st, int rowBase, int colBase,
                                           int k0, int tid){
#pragma unroll
    for (int j = 0; j < 4; ++j){
        int i = tid + j * 512;
        const __half* gp;
        uint32_t dst;
        if (i < 1024){
            int r = (i & 511) >> 2, g = i & 3;
            const __half* base = (i < 512) ? g_Ah : g_Al;
            gp = base + (size_t)(rowBase + r) * KK + k0 + g * 8;
            dst = st + (i < 512 ? 0u : 8192u) + swz(r, g);
        } else {
            int idx = i - 1024;
            int r = idx >> 2, g = idx & 3;
            gp = g_Bh + (size_t)(colBase + r) * KK + k0 + g * 8;
            dst = st + 16384u + swz(r, g);
        }
        cp16(dst, gp);
    }
    asm volatile("cp.async.commit_group;" ::: "memory");
}

// ---------------- fp16 split-K GEMM + fused epilogue ----------------
__global__ void __launch_bounds__(NTHREADS, 1)
mma_kernel(const float* __restrict__ Wout){
    extern __shared__ char smraw[];
    uint32_t sbase = smem_u32(smraw);
    int tid = threadIdx.x;
    int lane = tid & 31;
    int wid = tid >> 5;
    int warp_m = wid & 1;       // 0..1  -> 64 rows each
    int warp_n = wid >> 1;      // 0..7  -> 32 cols each
    int rowBase = blockIdx.y * BM;
    int colBase = blockIdx.x * BN;

    // ldmatrix within-tile offsets
    uint32_t offA[4][2];        // A: x4, rows = m
#pragma unroll
    for (int fm = 0; fm < 4; ++fm)
#pragma unroll
        for (int k16 = 0; k16 < 2; ++k16){
            uint32_t r = warp_m * 64 + fm * 16 + (lane & 15);
            uint32_t g = k16 * 2 + (lane >> 4);
            offA[fm][k16] = swz(r, g);
        }
    uint32_t offB2[2][2];       // B: x4 over fn-pairs
#pragma unroll
    for (int fp = 0; fp < 2; ++fp)
#pragma unroll
        for (int k16 = 0; k16 < 2; ++k16){
            uint32_t r = warp_n * 32 + fp * 16 + (((lane >> 4) & 1) * 8) + (lane & 7);
            uint32_t g = k16 * 2 + ((lane >> 3) & 1);
            offB2[fp][k16] = swz(r, g);
        }

    float acc[4][4][4];
#pragma unroll
    for (int fm = 0; fm < 4; ++fm)
#pragma unroll
        for (int fn = 0; fn < 4; ++fn)
#pragma unroll
            for (int q = 0; q < 4; ++q) acc[fm][fn][q] = 0.f;

    load_stage(sbase + 0 * STAGE_BYTES, rowBase, colBase, 0, tid);
    load_stage(sbase + 1 * STAGE_BYTES, rowBase, colBase, BK, tid);

    for (int it = 0; it < NKIT; ++it){
        asm volatile("cp.async.wait_group 1;" ::: "memory");
        __syncthreads();
        // refill the stage whose previous contents all warps finished reading
        if (it + 2 < NKIT)
            load_stage(sbase + ((it + 2) % NSTAGE) * STAGE_BYTES,
                       rowBase, colBase, (it + 2) * BK, tid);
        else
            asm volatile("cp.async.commit_group;" ::: "memory");

        uint32_t st = sbase + (it % NSTAGE) * STAGE_BYTES;
        uint32_t sAh = st, sAl = st + 8192u, sB = st + 16384u;

#pragma unroll
        for (int k16 = 0; k16 < 2; ++k16){
            uint32_t b[4][2];
#pragma unroll
            for (int fp = 0; fp < 2; ++fp)
                asm volatile("ldmatrix.sync.aligned.m8n8.x4.shared.b16 {%0,%1,%2,%3}, [%4];"
                    : "=r"(b[2*fp][0]), "=r"(b[2*fp][1]), "=r"(b[2*fp+1][0]), "=r"(b[2*fp+1][1])
                    : "r"(sB + offB2[fp][k16]));
            uint32_t a[4][4];
#pragma unroll
            for (int fm = 0; fm < 4; ++fm)
                asm volatile("ldmatrix.sync.aligned.m8n8.x4.shared.b16 {%0,%1,%2,%3}, [%4];"
                    : "=r"(a[fm][0]), "=r"(a[fm][1]), "=r"(a[fm][2]), "=r"(a[fm][3])
                    : "r"(sAh + offA[fm][k16]));
#pragma unroll
            for (int fm = 0; fm < 4; ++fm)
#pragma unroll
                for (int fn = 0; fn < 4; ++fn)
                    MMA16816(acc[fm][fn], a[fm], b[fn]);
            // low-A correction pass (reuse a regs)
#pragma unroll
            for (int fm = 0; fm < 4; ++fm)
                asm volatile("ldmatrix.sync.aligned.m8n8.x4.shared.b16 {%0,%1,%2,%3}, [%4];"
                    : "=r"(a[fm][0]), "=r"(a[fm][1]), "=r"(a[fm][2]), "=r"(a[fm][3])
                    : "r"(sAl + offA[fm][k16]));
#pragma unroll
            for (int fm = 0; fm < 4; ++fm)
#pragma unroll
                for (int fn = 0; fn < 4; ++fn)
                    MMA16816(acc[fm][fn], a[fm], b[fn]);
        }
    }

    // ---- epilogue: +decproj, tanh, dot W_out, reduce + atomic ----
    int b = rowBase >> 11;
    float wo[4][2], dp[4][2];
#pragma unroll
    for (int fn = 0; fn < 4; ++fn){
        int c0 = colBase + warp_n * 32 + fn * 8 + 2 * (lane & 3);
        wo[fn][0] = Wout[c0];               wo[fn][1] = Wout[c0 + 1];
        dp[fn][0] = g_decproj[b * AD + c0]; dp[fn][1] = g_decproj[b * AD + c0 + 1];
    }
    int g = lane >> 2;
#pragma unroll
    for (int fm = 0; fm < 4; ++fm){
        float s0 = 0.f, s1 = 0.f;
#pragma unroll
        for (int fn = 0; fn < 4; ++fn){
            s0 += tanhf(acc[fm][fn][0] + dp[fn][0]) * wo[fn][0];
            s0 += tanhf(acc[fm][fn][1] + dp[fn][1]) * wo[fn][1];
            s1 += tanhf(acc[fm][fn][2] + dp[fn][0]) * wo[fn][0];
            s1 += tanhf(acc[fm][fn][3] + dp[fn][1]) * wo[fn][1];
        }
        s0 += __shfl_xor_sync(~0u, s0, 1); s0 += __shfl_xor_sync(~0u, s0, 2);
        s1 += __shfl_xor_sync(~0u, s1, 1); s1 += __shfl_xor_sync(~0u, s1, 2);
        if ((lane & 3) == 0){
            int row = rowBase + warp_m * 64 + fm * 16 + g;
            atomicAdd(&g_score[row], s0);
            atomicAdd(&g_score[row + 8], s1);
        }
    }
}

// ---------------- softmax over T per batch ----------------
__global__ void softmax_kernel(const unsigned char* __restrict__ mask,
                               float* __restrict__ wout){
    __shared__ float red[256];
    int b = blockIdx.x;
    int tid = threadIdx.x;

    float local[8];
    float mx = -INFINITY;
#pragma unroll
    for (int i = 0; i < 8; ++i){
        int t = i * 256 + tid;
        float v = g_score[b * TT + t];
        if (mask[b * TT + t]) v = -INFINITY;
        local[i] = v;
        mx = fmaxf(mx, v);
    }
    red[tid] = mx; __syncthreads();
    for (int s = 128; s > 0; s >>= 1){
        if (tid < s) red[tid] = fmaxf(red[tid], red[tid + s]);
        __syncthreads();
    }
    mx = red[0]; __syncthreads();

    float sum = 0.f;
#pragma unroll
    for (int i = 0; i < 8; ++i){
        local[i] = expf(2.f * (local[i] - mx));
        sum += local[i];
    }
    red[tid] = sum; __syncthreads();
    for (int s = 128; s > 0; s >>= 1){
        if (tid < s) red[tid] += red[tid + s];
        __syncthreads();
    }
    float inv = 1.f / red[0];
#pragma unroll
    for (int i = 0; i < 8; ++i)
        wout[b * TT + i * 256 + tid] = local[i] * inv;
}

// ---------------- context ----------------
__global__ void context_kernel(const float* __restrict__ enc,
                               const float* __restrict__ w,
                               float* __restrict__ c){
    __shared__ float sw[256];
    int b = blockIdx.z;
    int e = blockIdx.x * 256 + threadIdx.x;
    int t0 = blockIdx.y * 256;
    sw[threadIdx.x] = w[b * TT + t0 + threadIdx.x];
    __syncthreads();

    const float* ep = enc + ((size_t)(b * TT + t0)) * ED + e;
    float acc = 0.f;
#pragma unroll 4
    for (int t = 0; t < 256; ++t)
        acc = fmaf(ep[(size_t)t * ED], sw[t], acc);
    atomicAdd(&c[b * ED + e], acc);
}

// ---------------- launch ----------------
extern "C" void kernel_launch(void* const* d_in, const int* in_sizes, int n_in,
                              void* d_out, int out_size){
    const float*         encoder_out = (const float*)d_in[0];
    const unsigned char* mask        = (const unsigned char*)d_in[1];
    const float*         decoder_h   = (const float*)d_in[2];
    const float*         attn_state  = (const float*)d_in[3];
    const float*         W_enc       = (const float*)d_in[4];
    const float*         b_enc       = (const float*)d_in[5];
    const float*         W_dec       = (const float*)d_in[6];
    const float*         W_attn      = (const float*)d_in[7];
    const float*         W_conv      = (const float*)d_in[8];
    const float*         W_out       = (const float*)d_in[9];
    const float*         b_out       = (const float*)d_in[10];

    float* out_c = (float*)d_out;               // [B, ED]
    float* out_w = (float*)d_out + BQ * ED;     // [B, T]

    cudaFuncSetAttribute(mma_kernel, cudaFuncAttributeMaxDynamicSharedMemorySize, SMEM_REQ);

    enc_split<<<(MM * ED / 4) / 256, 256>>>(encoder_out);
    conv_split<<<dim3(TT / 4, BQ), 256>>>(attn_state, W_conv);
    w_split<<<AD, 256>>>(W_enc, W_attn);
    dec_kernel<<<(BQ * AD * 32) / 256, 256>>>(decoder_h, W_dec, b_enc);
    init_kernel<<<MM / 256, 256>>>(b_out, out_c);
    mma_kernel<<<dim3(AD / BN, MM / BM), NTHREADS, SMEM_REQ>>>(W_out);
    softmax_kernel<<<BQ, 256>>>(mask, out_w);
    context_kernel<<<dim3(ED / 256, TT / 256, BQ), 256>>>(encoder_out, out_w, out_c);
}

// round 8
// speedup vs baseline: 3.3293x; 1.1220x over previous
#include <cuda_runtime.h>
#include <cuda_fp16.h>
#include <math.h>
#include <stdint.h>

// ---------------- problem constants ----------------
#define BQ 16
#define TT 2048
#define ED 1024
#define AD 512
#define DD 1024
#define CD 64
#define KSY 2
#define CK 15
#define KW 31
#define MM (BQ*TT)
#define KK 1088            // ED + CD concatenated K

// ---------------- GEMM tiling ----------------
#define BM 128
#define BN 256
#define BK 32
#define NKIT (KK/BK)       // 34
#define NENCKIT (ED/BK)    // 32 (chunks from encoder fp32)
#define NTILES ((MM/BM)*(AD/BN))   // 512
#define STAGE_BYTES 32768  // Ah 8K + Al 8K + B 16K
#define SMEM_REQ (3*STAGE_BYTES)
#define NTHREADS 512       // 16 warps: 2 (m) x 8 (n), warp tile 64x32
#define GRID_P 148         // persistent CTAs (1/SM)

// ---------------- scratch ----------------
__device__ __half g_Ahc[(size_t)MM*CD];   // conv features hi (fp16)
__device__ __half g_Alc[(size_t)MM*CD];   // conv features lo
__device__ __half g_Bh[(size_t)AD*KK];
__device__ float  g_decproj[BQ*AD];
__device__ float  g_score[MM];

// ---------------- helpers ----------------
__device__ __forceinline__ uint32_t smem_u32(const void* p){
    uint32_t a;
    asm("{ .reg .u64 t; cvta.to.shared.u64 t, %1; cvt.u32.u64 %0, t; }" : "=r"(a) : "l"(p));
    return a;
}
__device__ __forceinline__ void cp16(uint32_t dst, const void* src){
    asm volatile("cp.async.cg.shared.global [%0], [%1], 16;" :: "r"(dst), "l"(src) : "memory");
}
// 64B rows, 16B granules, XOR swizzle for conflict-free ldmatrix
__device__ __forceinline__ uint32_t swz(uint32_t r, uint32_t g){
    return r * 64u + ((g ^ ((r >> 1) & 3u)) << 4);
}
#define MMA16816(d, a, b) \
    asm volatile("mma.sync.aligned.m16n8k16.row.col.f32.f16.f16.f32 " \
        "{%0,%1,%2,%3}, {%4,%5,%6,%7}, {%8,%9}, {%0,%1,%2,%3};" \
        : "+f"((d)[0]), "+f"((d)[1]), "+f"((d)[2]), "+f"((d)[3]) \
        : "r"((a)[0]), "r"((a)[1]), "r"((a)[2]), "r"((a)[3]), \
          "r"((b)[0]), "r"((b)[1]))

// ---------------- prep: conv over time -> hi/lo fp16 [MM, 64] ----------------
__global__ void conv_split(const float* __restrict__ state,
                           const float* __restrict__ Wc){
    __shared__ float sW[CD * KSY * KW];
    int tid = threadIdx.x;
    for (int i = tid; i < CD * KSY * KW; i += 256) sW[i] = Wc[i];
    __syncthreads();

    int b = blockIdx.y;
    int c = tid & 63;
    int t = blockIdx.x * 4 + (tid >> 6);

    const float* s0 = state + (b * KSY + 0) * TT;
    const float* s1 = state + (b * KSY + 1) * TT;
    const float* w0 = &sW[(c * KSY + 0) * KW];
    const float* w1 = &sW[(c * KSY + 1) * KW];

    float acc = 0.f;
#pragma unroll
    for (int h = 0; h < KW; ++h){
        int tt = t + h - CK;
        bool ok = (tt >= 0) && (tt < TT);
        float v0 = ok ? s0[tt] : 0.f;
        float v1 = ok ? s1[tt] : 0.f;
        acc = fmaf(v0, w0[h], acc);
        acc = fmaf(v1, w1[h], acc);
    }
    __half hi = __float2half_rn(acc);
    size_t d = (size_t)(b * TT + t) * CD + c;
    g_Ahc[d] = hi;
    g_Alc[d] = __float2half_rn(acc - __half2float(hi));
}

// ---------------- prep: weights fp16, concatenated K ----------------
__global__ void w_split(const float* __restrict__ We, const float* __restrict__ Wa){
    int n = blockIdx.x;
    for (int k = threadIdx.x; k < KK; k += 256){
        float x = (k < ED) ? We[(size_t)n * ED + k] : Wa[n * CD + (k - ED)];
        g_Bh[(size_t)n * KK + k] = __float2half_rn(x);
    }
}

// ---------------- prep: decoder projection, warp-per-output ----------------
__global__ void dec_kernel(const float* __restrict__ h,
                           const float* __restrict__ Wd,
                           const float* __restrict__ be){
    int wgid = (blockIdx.x * 256 + threadIdx.x) >> 5;   // 0..8191
    int lane = threadIdx.x & 31;
    int b = wgid >> 9;
    int a = wgid & (AD - 1);
    const float4* hv = (const float4*)(h + b * DD) + lane;
    const float4* wv = (const float4*)(Wd + (size_t)a * DD) + lane;
    float acc = 0.f;
#pragma unroll
    for (int k = 0; k < 8; ++k){
        float4 x = hv[k * 32], w = wv[k * 32];
        acc = fmaf(x.x, w.x, acc); acc = fmaf(x.y, w.y, acc);
        acc = fmaf(x.z, w.z, acc); acc = fmaf(x.w, w.w, acc);
    }
#pragma unroll
    for (int s = 16; s > 0; s >>= 1) acc += __shfl_xor_sync(~0u, acc, s);
    if (lane == 0) g_decproj[wgid] = acc + be[a];
}

__global__ void init_kernel(const float* __restrict__ b_out, float* __restrict__ cctx){
    int i = blockIdx.x * 256 + threadIdx.x;
    if (i < MM) g_score[i] = b_out[0];
    if (i < BQ * ED) cctx[i] = 0.f;
}

// ---------------- persistent fused GEMM ----------------
__global__ void __launch_bounds__(NTHREADS, 1)
mma_kernel(const float* __restrict__ enc, const float* __restrict__ Wout){
    extern __shared__ char smraw[];
    uint32_t sbase = smem_u32(smraw);
    int tid = threadIdx.x;
    int lane = tid & 31;
    int wid = tid >> 5;
    int warp_m = wid & 1;       // 0..1  -> 64 rows each
    int warp_n = wid >> 1;      // 0..7  -> 32 cols each

    // A ldg/sts mapping: thread -> (row, 16B granule)
    int rT = tid >> 2, fqT = tid & 3;
    uint32_t stsOff = swz((uint32_t)rT, (uint32_t)fqT);

    // ldmatrix within-stage offsets (tile-independent)
    uint32_t offA[4][2];
#pragma unroll
    for (int fm = 0; fm < 4; ++fm)
#pragma unroll
        for (int k16 = 0; k16 < 2; ++k16){
            uint32_t r = warp_m * 64 + fm * 16 + (lane & 15);
            uint32_t g = k16 * 2 + (lane >> 4);
            offA[fm][k16] = swz(r, g);
        }
    uint32_t offB2[2][2];
#pragma unroll
    for (int fp = 0; fp < 2; ++fp)
#pragma unroll
        for (int k16 = 0; k16 < 2; ++k16){
            uint32_t r = warp_n * 32 + fp * 16 + (((lane >> 4) & 1) * 8) + (lane & 7);
            uint32_t g = k16 * 2 + ((lane >> 3) & 1);
            offB2[fp][k16] = swz(r, g) + 16384u;
        }

    for (int tile = blockIdx.x; tile < NTILES; tile += gridDim.x){
        int colBase = (tile & 1) * BN;
        int rowBase = (tile >> 1) * BM;
        const float* encRow = enc + (size_t)(rowBase + rT) * ED + fqT * 8;

        __syncthreads();   // previous tile's stage reads all retired

        float acc[4][4][4];
#pragma unroll
        for (int fm = 0; fm < 4; ++fm)
#pragma unroll
            for (int fn = 0; fn < 4; ++fn)
#pragma unroll
                for (int q = 0; q < 4; ++q) acc[fm][fn][q] = 0.f;

        float4 av0, av1;
        // ---- macro-like lambdas ----
        auto ldgA = [&](int k0){
            av0 = *(const float4*)(encRow + k0);
            av1 = *(const float4*)(encRow + k0 + 4);
        };
        auto stsA = [&](uint32_t st){
            float xs[8] = {av0.x, av0.y, av0.z, av0.w, av1.x, av1.y, av1.z, av1.w};
            uint32_t hq[4], lq[4];
#pragma unroll
            for (int j = 0; j < 4; ++j){
                __half h0 = __float2half_rn(xs[2*j]);
                __half h1 = __float2half_rn(xs[2*j+1]);
                __half l0 = __float2half_rn(xs[2*j]   - __half2float(h0));
                __half l1 = __float2half_rn(xs[2*j+1] - __half2float(h1));
                __half2 hh = __halves2half2(h0, h1);
                __half2 ll = __halves2half2(l0, l1);
                hq[j] = *(uint32_t*)&hh;
                lq[j] = *(uint32_t*)&ll;
            }
            asm volatile("st.shared.v4.b32 [%0], {%1,%2,%3,%4};"
                :: "r"(st + stsOff), "r"(hq[0]), "r"(hq[1]), "r"(hq[2]), "r"(hq[3]) : "memory");
            asm volatile("st.shared.v4.b32 [%0], {%1,%2,%3,%4};"
                :: "r"(st + 8192u + stsOff), "r"(lq[0]), "r"(lq[1]), "r"(lq[2]), "r"(lq[3]) : "memory");
        };
        auto cpB = [&](uint32_t st, int k0){
#pragma unroll
            for (int j = 0; j < 2; ++j){
                int i = tid + j * 512;
                int r = i >> 2, g = i & 3;
                cp16(st + 16384u + swz(r, g),
                     g_Bh + (size_t)(colBase + r) * KK + k0 + g * 8);
            }
        };
        auto cpConvA = [&](uint32_t st, int c0){
            cp16(st + stsOff, g_Ahc + (size_t)(rowBase + rT) * CD + c0 + fqT * 8);
            cp16(st + 8192u + stsOff, g_Alc + (size_t)(rowBase + rT) * CD + c0 + fqT * 8);
        };

        // ---- prologue ----
        ldgA(0);
        stsA(sbase);
        cpB(sbase, 0);
        asm volatile("cp.async.commit_group;" ::: "memory");
        ldgA(32);
        stsA(sbase + STAGE_BYTES);
        cpB(sbase + STAGE_BYTES, 32);
        asm volatile("cp.async.commit_group;" ::: "memory");
        ldgA(64);

        // ---- mainloop ----
        for (int it = 0; it < NKIT; ++it){
            asm volatile("cp.async.wait_group 1;" ::: "memory");
            __syncthreads();

            int nk = it + 2;
            uint32_t stn = sbase + (uint32_t)(nk % 3) * STAGE_BYTES;
            if (nk < NENCKIT){
                stsA(stn);
                cpB(stn, nk * BK);
                if (nk + 1 < NENCKIT) ldgA((nk + 1) * BK);
            } else if (nk < NKIT){
                cpConvA(stn, (nk - NENCKIT) * BK);
                cpB(stn, nk * BK);
            }
            asm volatile("cp.async.commit_group;" ::: "memory");

            uint32_t st = sbase + (uint32_t)(it % 3) * STAGE_BYTES;
#pragma unroll
            for (int k16 = 0; k16 < 2; ++k16){
                uint32_t b[4][2];
#pragma unroll
                for (int fp = 0; fp < 2; ++fp)
                    asm volatile("ldmatrix.sync.aligned.m8n8.x4.shared.b16 {%0,%1,%2,%3}, [%4];"
                        : "=r"(b[2*fp][0]), "=r"(b[2*fp][1]), "=r"(b[2*fp+1][0]), "=r"(b[2*fp+1][1])
                        : "r"(st + offB2[fp][k16]));
                uint32_t a[4][4];
#pragma unroll
                for (int fm = 0; fm < 4; ++fm)
                    asm volatile("ldmatrix.sync.aligned.m8n8.x4.shared.b16 {%0,%1,%2,%3}, [%4];"
                        : "=r"(a[fm][0]), "=r"(a[fm][1]), "=r"(a[fm][2]), "=r"(a[fm][3])
                        : "r"(st + offA[fm][k16]));
#pragma unroll
                for (int fm = 0; fm < 4; ++fm)
#pragma unroll
                    for (int fn = 0; fn < 4; ++fn)
                        MMA16816(acc[fm][fn], a[fm], b[fn]);
                // low-A correction pass (reuse a regs)
#pragma unroll
                for (int fm = 0; fm < 4; ++fm)
                    asm volatile("ldmatrix.sync.aligned.m8n8.x4.shared.b16 {%0,%1,%2,%3}, [%4];"
                        : "=r"(a[fm][0]), "=r"(a[fm][1]), "=r"(a[fm][2]), "=r"(a[fm][3])
                        : "r"(st + 8192u + offA[fm][k16]));
#pragma unroll
                for (int fm = 0; fm < 4; ++fm)
#pragma unroll
                    for (int fn = 0; fn < 4; ++fn)
                        MMA16816(acc[fm][fn], a[fm], b[fn]);
            }
        }

        // ---- epilogue: +decproj, tanh, dot W_out, reduce + atomic ----
        int b = rowBase >> 11;
        float wo[4][2], dp[4][2];
#pragma unroll
        for (int fn = 0; fn < 4; ++fn){
            int c0 = colBase + warp_n * 32 + fn * 8 + 2 * (lane & 3);
            wo[fn][0] = Wout[c0];               wo[fn][1] = Wout[c0 + 1];
            dp[fn][0] = g_decproj[b * AD + c0]; dp[fn][1] = g_decproj[b * AD + c0 + 1];
        }
        int g = lane >> 2;
#pragma unroll
        for (int fm = 0; fm < 4; ++fm){
            float s0 = 0.f, s1 = 0.f;
#pragma unroll
            for (int fn = 0; fn < 4; ++fn){
                s0 += tanhf(acc[fm][fn][0] + dp[fn][0]) * wo[fn][0];
                s0 += tanhf(acc[fm][fn][1] + dp[fn][1]) * wo[fn][1];
                s1 += tanhf(acc[fm][fn][2] + dp[fn][0]) * wo[fn][0];
                s1 += tanhf(acc[fm][fn][3] + dp[fn][1]) * wo[fn][1];
            }
            s0 += __shfl_xor_sync(~0u, s0, 1); s0 += __shfl_xor_sync(~0u, s0, 2);
            s1 += __shfl_xor_sync(~0u, s1, 1); s1 += __shfl_xor_sync(~0u, s1, 2);
            if ((lane & 3) == 0){
                int row = rowBase + warp_m * 64 + fm * 16 + g;
                atomicAdd(&g_score[row], s0);
                atomicAdd(&g_score[row + 8], s1);
            }
        }
    }
}

// ---------------- softmax over T per batch ----------------
__global__ void softmax_kernel(const unsigned char* __restrict__ mask,
                               float* __restrict__ wout){
    __shared__ float red[256];
    int b = blockIdx.x;
    int tid = threadIdx.x;

    float local[8];
    float mx = -INFINITY;
#pragma unroll
    for (int i = 0; i < 8; ++i){
        int t = i * 256 + tid;
        float v = g_score[b * TT + t];
        if (mask[b * TT + t]) v = -INFINITY;
        local[i] = v;
        mx = fmaxf(mx, v);
    }
    red[tid] = mx; __syncthreads();
    for (int s = 128; s > 0; s >>= 1){
        if (tid < s) red[tid] = fmaxf(red[tid], red[tid + s]);
        __syncthreads();
    }
    mx = red[0]; __syncthreads();

    float sum = 0.f;
#pragma unroll
    for (int i = 0; i < 8; ++i){
        local[i] = expf(2.f * (local[i] - mx));
        sum += local[i];
    }
    red[tid] = sum; __syncthreads();
    for (int s = 128; s > 0; s >>= 1){
        if (tid < s) red[tid] += red[tid + s];
        __syncthreads();
    }
    float inv = 1.f / red[0];
#pragma unroll
    for (int i = 0; i < 8; ++i)
        wout[b * TT + i * 256 + tid] = local[i] * inv;
}

// ---------------- context ----------------
__global__ void context_kernel(const float* __restrict__ enc,
                               const float* __restrict__ w,
                               float* __restrict__ c){
    __shared__ float sw[256];
    int b = blockIdx.z;
    int e = blockIdx.x * 256 + threadIdx.x;
    int t0 = blockIdx.y * 256;
    sw[threadIdx.x] = w[b * TT + t0 + threadIdx.x];
    __syncthreads();

    const float* ep = enc + ((size_t)(b * TT + t0)) * ED + e;
    float acc = 0.f;
#pragma unroll 4
    for (int t = 0; t < 256; ++t)
        acc = fmaf(ep[(size_t)t * ED], sw[t], acc);
    atomicAdd(&c[b * ED + e], acc);
}

// ---------------- launch ----------------
extern "C" void kernel_launch(void* const* d_in, const int* in_sizes, int n_in,
                              void* d_out, int out_size){
    const float*         encoder_out = (const float*)d_in[0];
    const unsigned char* mask        = (const unsigned char*)d_in[1];
    const float*         decoder_h   = (const float*)d_in[2];
    const float*         attn_state  = (const float*)d_in[3];
    const float*         W_enc       = (const float*)d_in[4];
    const float*         b_enc       = (const float*)d_in[5];
    const float*         W_dec       = (const float*)d_in[6];
    const float*         W_attn      = (const float*)d_in[7];
    const float*         W_conv      = (const float*)d_in[8];
    const float*         W_out       = (const float*)d_in[9];
    const float*         b_out       = (const float*)d_in[10];

    float* out_c = (float*)d_out;               // [B, ED]
    float* out_w = (float*)d_out + BQ * ED;     // [B, T]

    cudaFuncSetAttribute(mma_kernel, cudaFuncAttributeMaxDynamicSharedMemorySize, SMEM_REQ);

    conv_split<<<dim3(TT / 4, BQ), 256>>>(attn_state, W_conv);
    w_split<<<AD, 256>>>(W_enc, W_attn);
    dec_kernel<<<(BQ * AD * 32) / 256, 256>>>(decoder_h, W_dec, b_enc);
    init_kernel<<<MM / 256, 256>>>(b_out, out_c);
    mma_kernel<<<GRID_P, NTHREADS, SMEM_REQ>>>(encoder_out, W_out);
    softmax_kernel<<<BQ, 256>>>(mask, out_w);
    context_kernel<<<dim3(ED / 256, TT / 256, BQ), 256>>>(encoder_out, out_w, out_c);
}